// round 11
// baseline (speedup 1.0000x reference)
#include <cuda_runtime.h>

#define FULL 0xffffffffu

// Scratch (static device global — allocation-free). 16 MB, fits L2.
__device__ float g_partial[16][64][4096];  // per-(head-group, b, l) partials

__device__ __forceinline__ float tanh_approx(float v) {
    float r;
    asm("tanh.approx.f32 %0, %1;" : "=f"(r) : "f"(v));
    return r;
}

// ---------------------------------------------------------------------------
// K1 (fused): full-row scan + sigmoid + head reduction. NO carry prologue —
// each block owns 4 batches x 8 heads over ALL of j, iterating quarters
// internally with the scan carry in registers.
// grid (16 batch-quads, 16 head-groups of 8) = 256 blocks, 256 thr (8 warps).
// Warp = 1 head x 4 batches; the 4 chains batch into ONE warp scan per tile.
// W1+W2 L2 traffic: 256 blocks x 256KB = 64 MB (~6us floor).
// ---------------------------------------------------------------------------
__global__ __launch_bounds__(256, 3)
void nade_main_kernel(const float* __restrict__ x,
                      const float* __restrict__ W1,
                      const float* __restrict__ b1,
                      const float* __restrict__ W2)
{
    __shared__ float xs[4 * 1024];             // 16 KB: 4 batch quarter-rows
    __shared__ float red[8][4][128];           // 16 KB: warp partials

    const int b0   = blockIdx.x * 4;
    const int hg   = blockIdx.y;               // head group of 8
    const int tid  = threadIdx.x;
    const int w    = tid >> 5;                 // 8 warps, warp = 1 head
    const int lane = tid & 31;

    const float4* x4   = reinterpret_cast<const float4*>(x);
    const float4* W1_4 = reinterpret_cast<const float4*>(W1);
    const float4* W2_4 = reinterpret_cast<const float4*>(W2);
    float4*       xs4  = reinterpret_cast<float4*>(xs);

    const int i = hg * 8 + w;                  // this warp's head

    // cb[nb] = 0.5 * (b1[i] + running exclusive prefix for batch nb)
    float cb[4];
    {
        const float base = 0.5f * b1[i];
        #pragma unroll
        for (int nb = 0; nb < 4; nb++) cb[nb] = base;
    }

    for (int q = 0; q < 4; ++q) {
        // Stage this quarter's x rows for the 4 batches (1024 float4).
        __syncthreads();   // protect xs reuse from previous quarter
        for (int idx = tid; idx < 1024; idx += 256) {
            const int nb = idx >> 8;
            const int r  = idx & 255;
            xs4[idx] = x4[(b0 + nb) * 1024 + q * 256 + r];
        }
        __syncthreads();

        for (int t = 0; t < 8; ++t) {
            const int jv = t * 32 + lane;      // float4 idx within quarter

            float4 xv[4];
            #pragma unroll
            for (int nb = 0; nb < 4; nb++) xv[nb] = xs4[nb * 256 + jv];

            const float4 w1v = W1_4[i * 1024 + q * 256 + jv];
            const float4 w2v = W2_4[i * 1024 + q * 256 + jv];

            // Per-lane inclusive partials for the 4 batch chains.
            float s0[4], s1[4], s2[4], lt[4], inc[4];
            #pragma unroll
            for (int nb = 0; nb < 4; nb++) {
                s0[nb] = xv[nb].x * w1v.x;
                s1[nb] = fmaf(xv[nb].y, w1v.y, s0[nb]);
                s2[nb] = fmaf(xv[nb].z, w1v.z, s1[nb]);
                lt[nb] = fmaf(xv[nb].w, w1v.w, s2[nb]);
                inc[nb] = lt[nb];
            }

            // ONE batched warp scan for the 4 chains.
            #pragma unroll
            for (int o = 1; o < 32; o <<= 1) {
                const float v0 = __shfl_up_sync(FULL, inc[0], o);
                const float v1 = __shfl_up_sync(FULL, inc[1], o);
                const float v2 = __shfl_up_sync(FULL, inc[2], o);
                const float v3 = __shfl_up_sync(FULL, inc[3], o);
                if (lane >= o) {
                    inc[0] += v0; inc[1] += v1; inc[2] += v2; inc[3] += v3;
                }
            }
            float tot[4];
            #pragma unroll
            for (int nb = 0; nb < 4; nb++)
                tot[nb] = __shfl_sync(FULL, inc[nb], 31);

            float4 acc[4];
            #pragma unroll
            for (int nb = 0; nb < 4; nb++) {
                const float c2l = fmaf(0.5f, inc[nb] - lt[nb], cb[nb]);
                const float a0 = c2l;
                const float a1 = fmaf(0.5f, s0[nb], c2l);
                const float a2 = fmaf(0.5f, s1[nb], c2l);
                const float a3 = fmaf(0.5f, s2[nb], c2l);

                const float t0 = tanh_approx(a0);
                const float t1 = tanh_approx(a1);
                const float t2 = tanh_approx(a2);
                const float t3 = tanh_approx(a3);

                acc[nb].x = fmaf(0.5f, t0, 0.5f) * w2v.x;
                acc[nb].y = fmaf(0.5f, t1, 0.5f) * w2v.y;
                acc[nb].z = fmaf(0.5f, t2, 0.5f) * w2v.z;
                acc[nb].w = fmaf(0.5f, t3, 0.5f) * w2v.w;

                cb[nb] = fmaf(0.5f, tot[nb], cb[nb]);   // advance carry
            }

            // Stage partials: warp w, batch nb, 128 l values.
            #pragma unroll
            for (int nb = 0; nb < 4; nb++)
                reinterpret_cast<float4*>(&red[w][nb][0])[lane] = acc[nb];
            __syncthreads();

            // 256 threads reduce 512 outputs (2 each) over the 8 warps.
            #pragma unroll
            for (int k = 0; k < 2; k++) {
                const int oi  = tid + k * 256;
                const int nbr = oi >> 7;
                const int l   = oi & 127;
                float sum = 0.f;
                #pragma unroll
                for (int ww = 0; ww < 8; ++ww) sum += red[ww][nbr][l];
                g_partial[hg][b0 + nbr][q * 1024 + t * 128 + l] = sum;
            }
            __syncthreads();
        }
    }
}

// ---------------------------------------------------------------------------
// K2: combine 16 head-group partials + b2, accurate final sigmoid.
// ---------------------------------------------------------------------------
__global__ __launch_bounds__(256)
void nade_final_kernel(const float* __restrict__ b2,
                       float* __restrict__ out)
{
    const int idx4 = blockIdx.x * blockDim.x + threadIdx.x;  // 0..65535
    const int b = idx4 >> 10;
    const int r = idx4 & 1023;

    float4 s = reinterpret_cast<const float4*>(b2)[r];
    #pragma unroll
    for (int g = 0; g < 16; g++) {
        const float4 p = reinterpret_cast<const float4*>(&g_partial[g][b][0])[r];
        s.x += p.x; s.y += p.y; s.z += p.z; s.w += p.w;
    }
    float4 o;
    o.x = 1.0f / (1.0f + __expf(-s.x));
    o.y = 1.0f / (1.0f + __expf(-s.y));
    o.z = 1.0f / (1.0f + __expf(-s.z));
    o.w = 1.0f / (1.0f + __expf(-s.w));
    reinterpret_cast<float4*>(out)[idx4] = o;
}

extern "C" void kernel_launch(void* const* d_in, const int* in_sizes, int n_in,
                              void* d_out, int out_size)
{
    const float* x  = (const float*)d_in[0];
    const float* W1 = (const float*)d_in[1];
    const float* b1 = (const float*)d_in[2];
    const float* W2 = (const float*)d_in[3];
    const float* b2 = (const float*)d_in[4];

    nade_main_kernel<<<dim3(16, 16), 256>>>(x, W1, b1, W2);
    nade_final_kernel<<<256, 256>>>(b2, (float*)d_out);
}

// round 13
// speedup vs baseline: 1.1429x; 1.1429x over previous
#include <cuda_runtime.h>

#define FULL 0xffffffffu

// Scratch (static device globals — allocation-free).
__device__ float g_partial[8][64][4096];   // per-(head-group,b,l) partials (8 MB)
__device__ float g_S[3][64][128];          // quarter dot partials (q=1,2 used)
__device__ float g_C0[64][128];            // carry after quarter 0 = 0.5*(b1+S0)

__device__ __forceinline__ float tanh_approx(float v) {
    float r;
    asm("tanh.approx.f32 %0, %1;" : "=f"(r) : "f"(v));
    return r;
}

// ---------------------------------------------------------------------------
// Shared quarter-scan body (identical math/layout to the measured-best R10 K1).
// Block = 2 batches x 16 heads, one quarter. 8 warps; warp = 2 heads x 2 nb.
// ---------------------------------------------------------------------------
__device__ __forceinline__ void run_quarter(
    const float4* __restrict__ x4,
    const float4* __restrict__ W1_4,
    const float4* __restrict__ W2_4,
    float4* xs4, float red[8][2][128],
    int b0, int g, int q, int tid, int w, int lane, int i0, float cb[4])
{
    // Stage this quarter's x rows (2 batches, 256 float4 each).
    for (int idx = tid; idx < 512; idx += 256) {
        const int nb = idx >> 8;
        const int r  = idx & 255;
        xs4[idx] = x4[(b0 + nb) * 1024 + q * 256 + r];
    }
    __syncthreads();

    for (int t = 0; t < 8; ++t) {
        const int jv = t * 32 + lane;          // float4 idx within quarter

        float4 xv[2];
        xv[0] = xs4[jv];
        xv[1] = xs4[256 + jv];

        float4 acc[2];
        acc[0] = make_float4(0.f, 0.f, 0.f, 0.f);
        acc[1] = make_float4(0.f, 0.f, 0.f, 0.f);

        float4 w1v[2], w2v[2];
        #pragma unroll
        for (int h = 0; h < 2; h++) {
            w1v[h] = W1_4[(i0 + h) * 1024 + q * 256 + jv];
            w2v[h] = W2_4[(i0 + h) * 1024 + q * 256 + jv];
        }

        // Per-lane inclusive partials for all 4 chains (h x nb).
        float s0[4], s1[4], s2[4], lt[4], inc[4];
        #pragma unroll
        for (int h = 0; h < 2; h++)
            #pragma unroll
            for (int nb = 0; nb < 2; nb++) {
                const int c = h * 2 + nb;
                s0[c] = xv[nb].x * w1v[h].x;
                s1[c] = fmaf(xv[nb].y, w1v[h].y, s0[c]);
                s2[c] = fmaf(xv[nb].z, w1v[h].z, s1[c]);
                lt[c] = fmaf(xv[nb].w, w1v[h].w, s2[c]);
                inc[c] = lt[c];
            }

        // ONE batched warp scan for all 4 chains.
        #pragma unroll
        for (int o = 1; o < 32; o <<= 1) {
            const float v0 = __shfl_up_sync(FULL, inc[0], o);
            const float v1 = __shfl_up_sync(FULL, inc[1], o);
            const float v2 = __shfl_up_sync(FULL, inc[2], o);
            const float v3 = __shfl_up_sync(FULL, inc[3], o);
            if (lane >= o) {
                inc[0] += v0; inc[1] += v1; inc[2] += v2; inc[3] += v3;
            }
        }
        float tot[4];
        #pragma unroll
        for (int c = 0; c < 4; c++)
            tot[c] = __shfl_sync(FULL, inc[c], 31);

        #pragma unroll
        for (int h = 0; h < 2; h++)
            #pragma unroll
            for (int nb = 0; nb < 2; nb++) {
                const int c = h * 2 + nb;
                const float c2l = fmaf(0.5f, inc[c] - lt[c], cb[c]);
                const float a0 = c2l;
                const float a1 = fmaf(0.5f, s0[c], c2l);
                const float a2 = fmaf(0.5f, s1[c], c2l);
                const float a3 = fmaf(0.5f, s2[c], c2l);

                const float t0 = tanh_approx(a0);
                const float t1 = tanh_approx(a1);
                const float t2 = tanh_approx(a2);
                const float t3 = tanh_approx(a3);

                acc[nb].x = fmaf(fmaf(0.5f, t0, 0.5f), w2v[h].x, acc[nb].x);
                acc[nb].y = fmaf(fmaf(0.5f, t1, 0.5f), w2v[h].y, acc[nb].y);
                acc[nb].z = fmaf(fmaf(0.5f, t2, 0.5f), w2v[h].z, acc[nb].z);
                acc[nb].w = fmaf(fmaf(0.5f, t3, 0.5f), w2v[h].w, acc[nb].w);

                cb[c] = fmaf(0.5f, tot[c], cb[c]);
            }

        // Stage partials: warp w, batch nb, 128 l values.
        reinterpret_cast<float4*>(&red[w][0][0])[lane] = acc[0];
        reinterpret_cast<float4*>(&red[w][1][0])[lane] = acc[1];
        __syncthreads();

        // 256 threads reduce 256 outputs: nb = tid>>7, l = tid&127.
        {
            const int nbr = tid >> 7;
            const int l   = tid & 127;
            float sum = 0.f;
            #pragma unroll
            for (int ww = 0; ww < 8; ++ww) sum += red[ww][nbr][l];
            g_partial[g][b0 + nbr][q * 1024 + t * 128 + l] = sum;
        }
        __syncthreads();
    }
}

// ---------------------------------------------------------------------------
// Kernel A: role-split.
//   blocks 0..255   : q=0 scan (32 bq x 8 hg). End-carry written to g_C0 (=S0 free).
//   blocks 256..767 : carry dots S_q for q in {1,2} (16 bq4 x 16 hg8 x 2 q).
// The latency-bound dot blocks overlap with the MUFU-bound scan blocks.
// ---------------------------------------------------------------------------
__global__ __launch_bounds__(256, 3)
void nade_a_kernel(const float* __restrict__ x,
                   const float* __restrict__ W1,
                   const float* __restrict__ b1,
                   const float* __restrict__ W2)
{
    __shared__ float xs[2 * 1024];             // 8 KB
    __shared__ float red[8][2][128];           // 4 KB

    const int tid  = threadIdx.x;
    const int w    = tid >> 5;
    const int lane = tid & 31;

    const float4* x4   = reinterpret_cast<const float4*>(x);
    const float4* W1_4 = reinterpret_cast<const float4*>(W1);

    if (blockIdx.x < 256) {
        // ---- q=0 scan role ----
        const int b0 = (blockIdx.x & 31) * 2;
        const int g  = (blockIdx.x >> 5) & 7;
        const int i0 = g * 16 + w * 2;

        float cb[4];
        #pragma unroll
        for (int h = 0; h < 2; h++) {
            const float base = 0.5f * b1[i0 + h];
            cb[h * 2 + 0] = base;
            cb[h * 2 + 1] = base;
        }

        run_quarter(x4, W1_4, reinterpret_cast<const float4*>(W2),
                    reinterpret_cast<float4*>(xs), red,
                    b0, g, 0, tid, w, lane, i0, cb);

        // End-carry after quarter 0 = 0.5*(b1 + S0): q=1 blocks read this.
        if (lane == 0) {
            #pragma unroll
            for (int h = 0; h < 2; h++)
                #pragma unroll
                for (int nb = 0; nb < 2; nb++)
                    g_C0[b0 + nb][i0 + h] = cb[h * 2 + nb];
        }
    } else {
        // ---- carry-dot role: S_q[b][i] for q in {1,2} ----
        const int r  = blockIdx.x - 256;       // 0..511
        const int bq = r & 15;                 // batch quad
        const int hg = (r >> 4) & 15;          // head chunk of 8
        const int q  = 1 + (r >> 8);           // 1 or 2

        const int i = hg * 8 + w;              // warp's head

        float acc[4] = {0.f, 0.f, 0.f, 0.f};
        #pragma unroll
        for (int c = 0; c < 8; c++) {
            const int j4 = q * 256 + c * 32 + lane;
            const float4 w1v = W1_4[i * 1024 + j4];
            #pragma unroll
            for (int nb = 0; nb < 4; nb++) {
                const float4 xv = x4[(bq * 4 + nb) * 1024 + j4];
                acc[nb] = fmaf(xv.x, w1v.x, fmaf(xv.y, w1v.y,
                          fmaf(xv.z, w1v.z, fmaf(xv.w, w1v.w, acc[nb]))));
            }
        }
        #pragma unroll
        for (int o = 16; o > 0; o >>= 1) {
            #pragma unroll
            for (int nb = 0; nb < 4; nb++)
                acc[nb] += __shfl_down_sync(FULL, acc[nb], o);
        }
        if (lane == 0) {
            #pragma unroll
            for (int nb = 0; nb < 4; nb++)
                g_S[q][bq * 4 + nb][i] = acc[nb];
        }
    }
}

// ---------------------------------------------------------------------------
// Kernel B: q = 1..3 scans. grid (32 bq, 8 hg, 3) = 768 blocks, 256 thr.
// Carry-in: C0 (+ 0.5*S1 for q>=2, + 0.5*S2 for q==3).
// ---------------------------------------------------------------------------
__global__ __launch_bounds__(256, 3)
void nade_b_kernel(const float* __restrict__ x,
                   const float* __restrict__ W1,
                   const float* __restrict__ W2)
{
    __shared__ float xs[2 * 1024];
    __shared__ float red[8][2][128];

    const int b0   = blockIdx.x * 2;
    const int g    = blockIdx.y;
    const int q    = blockIdx.z + 1;           // 1..3
    const int tid  = threadIdx.x;
    const int w    = tid >> 5;
    const int lane = tid & 31;

    const int i0 = g * 16 + w * 2;

    float cb[4];
    #pragma unroll
    for (int h = 0; h < 2; h++)
        #pragma unroll
        for (int nb = 0; nb < 2; nb++) {
            float c = g_C0[b0 + nb][i0 + h];
            if (q >= 2) c = fmaf(0.5f, g_S[1][b0 + nb][i0 + h], c);
            if (q >= 3) c = fmaf(0.5f, g_S[2][b0 + nb][i0 + h], c);
            cb[h * 2 + nb] = c;
        }

    run_quarter(reinterpret_cast<const float4*>(x),
                reinterpret_cast<const float4*>(W1),
                reinterpret_cast<const float4*>(W2),
                reinterpret_cast<float4*>(xs), red,
                b0, g, q, tid, w, lane, i0, cb);
}

// ---------------------------------------------------------------------------
// Kernel C: combine 8 group partials + b2, accurate final sigmoid.
// 131072 threads, float2 each (more MLP, latency-bound kernel).
// ---------------------------------------------------------------------------
__global__ __launch_bounds__(256)
void nade_final_kernel(const float* __restrict__ b2,
                       float* __restrict__ out)
{
    const int idx2 = blockIdx.x * blockDim.x + threadIdx.x;  // 0..131071
    const int b = idx2 >> 11;
    const int r = idx2 & 2047;

    float2 s = reinterpret_cast<const float2*>(b2)[r];
    #pragma unroll
    for (int g = 0; g < 8; g++) {
        const float2 p = reinterpret_cast<const float2*>(&g_partial[g][b][0])[r];
        s.x += p.x; s.y += p.y;
    }
    float2 o;
    o.x = 1.0f / (1.0f + __expf(-s.x));
    o.y = 1.0f / (1.0f + __expf(-s.y));
    reinterpret_cast<float2*>(out)[idx2] = o;
}

extern "C" void kernel_launch(void* const* d_in, const int* in_sizes, int n_in,
                              void* d_out, int out_size)
{
    const float* x  = (const float*)d_in[0];
    const float* W1 = (const float*)d_in[1];
    const float* b1 = (const float*)d_in[2];
    const float* W2 = (const float*)d_in[3];
    const float* b2 = (const float*)d_in[4];

    nade_a_kernel<<<768, 256>>>(x, W1, b1, W2);
    nade_b_kernel<<<dim3(32, 8, 3), 256>>>(x, W1, W2);
    nade_final_kernel<<<512, 256>>>(b2, (float*)d_out);
}